// round 14
// baseline (speedup 1.0000x reference)
#include <cuda_runtime.h>
#include <cuda_fp16.h>
#include <cstdint>

// ---------------------------------------------------------------------------
// out[8192,4096] = x[8192,4096]_fp32 @ sign(fp16(w[4096,4096]))
//
// R14: rt(HMMA.f16acc) rate experiment at the issue limit.
// R12 pipeline (512 thr, BM128xBN256, 4-stage cp.async + warp-level mbarrier)
// with fp16 chunk accumulators: 4 chained m16n8k16.f16 MMAs per K=64 iter,
// flushed into fp32 registers each iteration (R9-validated: rel_err 3.88e-4).
// B fragments processed in pairs to fit the 128-reg cap at 512 threads.
// f32-acc wall = 11.6 cyc/SMSP (R12 at 100% of it); if f16acc issues at
// ~5.8 cyc the GEMM floor halves to ~350us.
// ---------------------------------------------------------------------------

#define M_DIM 8192
#define N_DIM 4096
#define K_DIM 4096

#define BM 128
#define BN 256
#define BK 64
#define STAGES 4
#define THREADS 512
#define NWARPS (THREADS / 32)
#define NKI (K_DIM / BK)   // 64

#define A_TILE_BYTES (BM * BK * 2)            // 16384
#define B_TILE_BYTES (BN * BK * 2)            // 32768
#define STAGE_BYTES  (A_TILE_BYTES + B_TILE_BYTES)   // 49152
#define SMEM_DYN     (1024 + 1024 + STAGES * STAGE_BYTES)  // 198656

// ------------------------------ scratch -----------------------------------
__device__ __align__(1024) __half g_xh[(size_t)M_DIM * K_DIM];   // 64 MB
__device__ __align__(1024) __half g_wbt[(size_t)N_DIM * K_DIM];  // 32 MB

// --------------------------- convert kernels -------------------------------
__global__ void __launch_bounds__(256, 8) cvt_x_kernel(
    const float4* __restrict__ x, uint4* __restrict__ xh, int n8)
{
    int i = blockIdx.x * blockDim.x + threadIdx.x;
    if (i >= n8) return;
    float4 v0 = x[i * 2];
    float4 v1 = x[i * 2 + 1];
    __half2 a = __floats2half2_rn(v0.x, v0.y);
    __half2 b = __floats2half2_rn(v0.z, v0.w);
    __half2 c = __floats2half2_rn(v1.x, v1.y);
    __half2 d = __floats2half2_rn(v1.z, v1.w);
    uint4 o;
    o.x = *reinterpret_cast<uint32_t*>(&a);
    o.y = *reinterpret_cast<uint32_t*>(&b);
    o.z = *reinterpret_cast<uint32_t*>(&c);
    o.w = *reinterpret_cast<uint32_t*>(&d);
    xh[i] = o;
}

// w[K,N] fp32 -> wbt[N,K] fp16 sign(fp16(w)); 64x64 tiles, vectorized IO
__global__ void __launch_bounds__(256, 4) cvt_w_kernel(
    const float* __restrict__ w, __half* __restrict__ wbt)
{
    __shared__ __half t[64][72];
    const int n0 = blockIdx.x * 64;
    const int k0 = blockIdx.y * 64;
    const int tid = threadIdx.x;

    const int lk = tid >> 4;
    const int ln = (tid & 15) << 2;
    #pragma unroll
    for (int i = 0; i < 4; i++) {
        int k = lk + i * 16;
        float4 v = *reinterpret_cast<const float4*>(
            w + (size_t)(k0 + k) * N_DIM + n0 + ln);
        float f[4] = {v.x, v.y, v.z, v.w};
        #pragma unroll
        for (int j = 0; j < 4; j++) {
            float hf = __half2float(__float2half_rn(f[j]));
            float s = (hf > 0.f) ? 1.f : ((hf < 0.f) ? -1.f : 0.f);
            t[ln + j][k] = __float2half_rn(s);
        }
    }
    __syncthreads();

    const int sn = tid >> 2;
    const int sk = (tid & 3) << 3;
    #pragma unroll
    for (int i = 0; i < 2; i++) {
        int kk = sk + i * 32;
        uint4 o = *reinterpret_cast<uint4*>(&t[sn][kk]);
        *reinterpret_cast<uint4*>(
            wbt + (size_t)(n0 + sn) * K_DIM + k0 + kk) = o;
    }
}

// dummy launch: keeps ncu's "-s 5 -c 1" window on the GEMM
__global__ void prof_pad_kernel() {}

// ------------------------------ PTX helpers -------------------------------
__device__ __forceinline__ uint32_t smem_u32(const void* p) {
    uint32_t a;
    asm("{ .reg .u64 t; cvta.to.shared.u64 t, %1; cvt.u32.u64 %0, t; }"
        : "=r"(a) : "l"(p));
    return a;
}

__device__ __forceinline__ uint32_t elect_one() {
    uint32_t pred;
    asm volatile(
        "{\n\t.reg .pred p;\n\t"
        "elect.sync _|p, 0xFFFFFFFF;\n\t"
        "selp.b32 %0, 1, 0, p;\n\t}"
        : "=r"(pred));
    return pred;
}

__device__ __forceinline__ void cp_async_16(uint32_t smem_dst, const void* gmem_src) {
    asm volatile("cp.async.cg.shared.global [%0], [%1], 16;"
                 :: "r"(smem_dst), "l"(gmem_src));
}

#define MBARRIER_INIT(addr, count) \
    asm volatile("mbarrier.init.shared.b64 [%0], %1;" \
                 :: "r"((uint32_t)(addr)), "r"((uint32_t)(count)) : "memory")

#define MBARRIER_ARRIVE(addr) \
    asm volatile("mbarrier.arrive.shared.b64 _, [%0];" \
                 :: "r"((uint32_t)(addr)) : "memory")

#define CPASYNC_MBAR_ARRIVE_NOINC(addr) \
    asm volatile("cp.async.mbarrier.arrive.noinc.shared.b64 [%0];" \
                 :: "r"((uint32_t)(addr)) : "memory")

#define MBARRIER_WAIT_PARITY(mbar_smem_addr, phase_parity) do { \
    uint32_t _mbar = (uint32_t)(mbar_smem_addr); \
    uint32_t _parity = (uint32_t)(phase_parity); \
    uint32_t _done; \
    asm volatile( \
        "{\n\t.reg .pred p;\n\t" \
        "mbarrier.try_wait.parity.acquire.cta.shared::cta.b64 p, [%1], %2;\n\t" \
        "selp.b32 %0, 1, 0, p;\n\t}" \
        : "=r"(_done) : "r"(_mbar), "r"(_parity) : "memory"); \
    if (!_done) { \
        asm volatile( \
            "{\n\t.reg .pred P1;\n\t" \
            "WAIT_LOOP_%=:\n\t" \
            "mbarrier.try_wait.parity.acquire.cta.shared::cta.b64 P1, [%0], %1, 0x989680;\n\t" \
            "@P1 bra.uni WAIT_DONE_%=;\n\t" \
            "bra.uni WAIT_LOOP_%=;\n\t" \
            "WAIT_DONE_%=:\n\t}" \
            :: "r"(_mbar), "r"(_parity) : "memory"); \
    } \
} while(0)

// elected single-lane wait + warp reconvergence
#define WARP_WAIT_PARITY(addr, parity) do { \
    if (elect_one()) { MBARRIER_WAIT_PARITY(addr, parity); } \
    __syncwarp(); \
} while (0)

__device__ __forceinline__ void ldmatrix_x4(uint32_t& r0, uint32_t& r1,
                                            uint32_t& r2, uint32_t& r3, uint32_t addr) {
    asm volatile("ldmatrix.sync.aligned.m8n8.x4.shared.b16 {%0,%1,%2,%3}, [%4];"
                 : "=r"(r0), "=r"(r1), "=r"(r2), "=r"(r3) : "r"(addr));
}

// fp16-accumulate MMA: C/D are 2 regs of f16x2
__device__ __forceinline__ void mma_16816_f16(uint32_t* c, const uint32_t* a,
                                              const uint32_t* b) {
    asm volatile(
        "mma.sync.aligned.m16n8k16.row.col.f16.f16.f16.f16 "
        "{%0,%1}, {%2,%3,%4,%5}, {%6,%7}, {%0,%1};"
        : "+r"(c[0]), "+r"(c[1])
        : "r"(a[0]), "r"(a[1]), "r"(a[2]), "r"(a[3]), "r"(b[0]), "r"(b[1]));
}

// swizzle within a [rows][BK] fp16 tile, 128B rows: 16B chunk XOR (row & 7)
__device__ __forceinline__ uint32_t tile_off(int row, int chunk) {
    return (uint32_t)(row * 128 + ((chunk ^ (row & 7)) << 4));
}

// ------------------------------ GEMM kernel --------------------------------
__global__ void __launch_bounds__(THREADS, 1) bgemm_mma_kernel(
    const __half* __restrict__ A,   // [M,K]
    const __half* __restrict__ B,   // [N,K]
    float* __restrict__ out)
{
    extern __shared__ uint8_t smem_raw[];
    uint32_t raw = smem_u32(smem_raw);
    const uint32_t hdr   = (raw + 1023u) & ~1023u;
    const uint32_t tiles = hdr + 1024u;

    #define FULL_BAR(s)  (hdr + (uint32_t)(s) * 8u)
    #define EMPTY_BAR(s) (hdr + 64u + (uint32_t)(s) * 8u)

    const int tid  = threadIdx.x;
    const int wid  = tid >> 5;
    const int lane = tid & 31;
    const int m0 = blockIdx.x * BM;
    const int n0 = blockIdx.y * BN;

    const int warp_m = wid & 3;   // 4 warps over M: 32 rows each
    const int warp_n = wid >> 2;  // 4 warps over N: 64 cols each

    const int ld_row0  = tid >> 3;   // 0..63
    const int ld_chunk = tid & 7;    // 0..7

    auto load_stage = [&](int slot, int kt) {
        const uint32_t sA = tiles + slot * STAGE_BYTES;
        const uint32_t sB = sA + A_TILE_BYTES;
        const int kcol = kt * BK + ld_chunk * 8;
        #pragma unroll
        for (int p = 0; p < 2; p++) {
            int row = ld_row0 + p * 64;
            cp_async_16(sA + tile_off(row, ld_chunk),
                        A + (size_t)(m0 + row) * K_DIM + kcol);
        }
        #pragma unroll
        for (int p = 0; p < 4; p++) {
            int row = ld_row0 + p * 64;
            cp_async_16(sB + tile_off(row, ld_chunk),
                        B + (size_t)(n0 + row) * K_DIM + kcol);
        }
        CPASYNC_MBAR_ARRIVE_NOINC(FULL_BAR(slot));
    };

    if (tid == 0) {
        #pragma unroll
        for (int s = 0; s < STAGES; s++) {
            MBARRIER_INIT(FULL_BAR(s), THREADS);
            MBARRIER_INIT(EMPTY_BAR(s), NWARPS);
        }
        asm volatile("fence.proxy.async.shared::cta;" ::: "memory");
    }
    __syncthreads();

    const int lrow = lane & 15;
    const int lsel = lane >> 4;

    uint32_t a_off[2], b_off[4];
    #pragma unroll
    for (int mi = 0; mi < 2; mi++)
        a_off[mi] = tile_off(warp_m * 32 + mi * 16 + lrow, lsel);
    #pragma unroll
    for (int nj = 0; nj < 4; nj++)
        b_off[nj] = tile_off(warp_n * 64 + nj * 16 + lrow, lsel);

    float acc[2][8][4];
    #pragma unroll
    for (int mi = 0; mi < 2; mi++)
        #pragma unroll
        for (int ni = 0; ni < 8; ni++)
            #pragma unroll
            for (int j = 0; j < 4; j++) acc[mi][ni][j] = 0.f;

    // prologue: fill stages 0..2
    #pragma unroll
    for (int s = 0; s < STAGES - 1; s++) {
        WARP_WAIT_PARITY(EMPTY_BAR(s), 1);
        load_stage(s, s);
    }

    for (int it = 0; it < NKI; it++) {
        const int s = it & 3;
        const uint32_t sA = tiles + s * STAGE_BYTES;
        const uint32_t sB = sA + A_TILE_BYTES;

        WARP_WAIT_PARITY(FULL_BAR(s), (it >> 2) & 1);

        // fp16 chunk accumulators, zeroed each k-iter
        uint32_t acch[2][8][2];
        #pragma unroll
        for (int mi = 0; mi < 2; mi++)
            #pragma unroll
            for (int ni = 0; ni < 8; ni++) {
                acch[mi][ni][0] = 0u; acch[mi][ni][1] = 0u;
            }

        #pragma unroll
        for (int kk = 0; kk < BK / 16; kk++) {
            const uint32_t kx = (uint32_t)kk << 5;

            uint32_t a[2][4];
            #pragma unroll
            for (int mi = 0; mi < 2; mi++)
                ldmatrix_x4(a[mi][0], a[mi][1], a[mi][2], a[mi][3],
                            (sA + a_off[mi]) ^ kx);

            // B in pairs (nj -> 2 n-frags) to keep live b regs at 8
            #pragma unroll
            for (int njp = 0; njp < 2; njp++) {
                uint32_t b[4][2];
                #pragma unroll
                for (int q = 0; q < 2; q++) {
                    int nj = njp * 2 + q;
                    uint32_t r0, r1, r2, r3;
                    ldmatrix_x4(r0, r1, r2, r3, (sB + b_off[nj]) ^ kx);
                    b[q * 2 + 0][0] = r0; b[q * 2 + 1][0] = r1;
                    b[q * 2 + 0][1] = r2; b[q * 2 + 1][1] = r3;
                }

                // release the stage after our LAST smem read of it
                if (kk == BK / 16 - 1 && njp == 1) {
                    __syncwarp();
                    if (elect_one()) MBARRIER_ARRIVE(EMPTY_BAR(s));
                }

                #pragma unroll
                for (int mi = 0; mi < 2; mi++)
                    #pragma unroll
                    for (int q = 0; q < 4; q++)
                        mma_16816_f16(acch[mi][njp * 4 + q], a[mi], b[q]);
            }
        }

        // producer refill first (cp.async overlaps the flush below)
        const int kt = it + STAGES - 1;
        if (kt < NKI) {
            const int ps = kt & 3;
            WARP_WAIT_PARITY(EMPTY_BAR(ps), ((kt >> 2) & 1) ^ 1);
            load_stage(ps, kt);
        }

        // flush fp16 chunk sums into fp32 accumulators
        #pragma unroll
        for (int mi = 0; mi < 2; mi++)
            #pragma unroll
            for (int ni = 0; ni < 8; ni++) {
                float2 f0 = __half22float2(
                    *reinterpret_cast<__half2*>(&acch[mi][ni][0]));
                float2 f1 = __half22float2(
                    *reinterpret_cast<__half2*>(&acch[mi][ni][1]));
                acc[mi][ni][0] += f0.x; acc[mi][ni][1] += f0.y;
                acc[mi][ni][2] += f1.x; acc[mi][ni][3] += f1.y;
            }
    }

    // ------------------------------ epilogue -------------------------------
    const int tq = lane >> 2;
    const int tp = lane & 3;
    #pragma unroll
    for (int mi = 0; mi < 2; mi++) {
        #pragma unroll
        for (int ni = 0; ni < 8; ni++) {
            int r = m0 + warp_m * 32 + mi * 16 + tq;
            int c = n0 + warp_n * 64 + ni * 8 + tp * 2;
            float2 v0 = make_float2(acc[mi][ni][0], acc[mi][ni][1]);
            float2 v1 = make_float2(acc[mi][ni][2], acc[mi][ni][3]);
            *reinterpret_cast<float2*>(out + (size_t)r * N_DIM + c) = v0;
            *reinterpret_cast<float2*>(out + (size_t)(r + 8) * N_DIM + c) = v1;
        }
    }
}

// ------------------------------- host side --------------------------------
extern "C" void kernel_launch(void* const* d_in, const int* in_sizes, int n_in,
                              void* d_out, int out_size)
{
    const float* x = (const float*)d_in[0];
    const float* w = (const float*)d_in[1];
    float* out = (float*)d_out;

    void *xh_ptr = nullptr, *wbt_ptr = nullptr;
    cudaGetSymbolAddress(&xh_ptr, g_xh);
    cudaGetSymbolAddress(&wbt_ptr, g_wbt);

    {
        int n8 = (M_DIM * K_DIM) / 8;
        cvt_x_kernel<<<(n8 + 255) / 256, 256>>>((const float4*)x, (uint4*)xh_ptr, n8);
        dim3 gw(N_DIM / 64, K_DIM / 64);
        cvt_w_kernel<<<gw, 256>>>(w, (__half*)wbt_ptr);
    }

    // pad launch so ncu's "-s 5 -c 1" window lands on the GEMM
    prof_pad_kernel<<<1, 32>>>();

    cudaFuncSetAttribute(bgemm_mma_kernel,
                         cudaFuncAttributeMaxDynamicSharedMemorySize, SMEM_DYN);

    dim3 grid(M_DIM / BM, N_DIM / BN);  // (64, 16)
    bgemm_mma_kernel<<<grid, THREADS, SMEM_DYN>>>(
        (const __half*)xh_ptr, (const __half*)wbt_ptr, out);
}

// round 15
// speedup vs baseline: 1.1285x; 1.1285x over previous
#include <cuda_runtime.h>
#include <cuda_fp16.h>
#include <cstdint>

// ---------------------------------------------------------------------------
// out[8192,4096] = x[8192,4096]_fp32 @ sign(fp16(w[4096,4096]))
//
// R15: GEMM = R12 exactly (100.0% of the measured legacy-HMMA issue wall:
// rt ~= 11.6 cyc/SMSP regardless of accumulator type; 67.1M HMMAs -> 691us).
// Converts fused into ONE kernel: w-transpose blocks (latency-bound) and
// x-convert blocks (DRAM-bound) interleaved across SMs; x path widened to
// 16 floats/thread. Two pads keep the GEMM at ncu launch position 3.
// ---------------------------------------------------------------------------

#define M_DIM 8192
#define N_DIM 4096
#define K_DIM 4096

#define BM 128
#define BN 256
#define BK 64
#define STAGES 4
#define THREADS 512
#define NWARPS (THREADS / 32)
#define NKI (K_DIM / BK)   // 64

#define A_TILE_BYTES (BM * BK * 2)            // 16384
#define B_TILE_BYTES (BN * BK * 2)            // 32768
#define STAGE_BYTES  (A_TILE_BYTES + B_TILE_BYTES)   // 49152
#define SMEM_DYN     (1024 + 1024 + STAGES * STAGE_BYTES)  // 198656

#define W_BLOCKS ((N_DIM / 64) * (K_DIM / 64))          // 4096
#define X_BLOCKS ((M_DIM * K_DIM) / (256 * 16))         // 8192

// ------------------------------ scratch -----------------------------------
__device__ __align__(1024) __half g_xh[(size_t)M_DIM * K_DIM];   // 64 MB
__device__ __align__(1024) __half g_wbt[(size_t)N_DIM * K_DIM];  // 32 MB

// --------------------------- fused convert kernel ---------------------------
// blocks [0, W_BLOCKS): w[K,N] fp32 -> wbt[N,K] fp16 sign(fp16(w)), 64x64 tile
// blocks [W_BLOCKS, W_BLOCKS+X_BLOCKS): x fp32 -> fp16, 16 floats/thread
__global__ void __launch_bounds__(256, 8) cvt_fused_kernel(
    const float4* __restrict__ x, uint4* __restrict__ xh,
    const float*  __restrict__ w, __half* __restrict__ wbt)
{
    __shared__ __half t[64][72];
    const int tid = threadIdx.x;

    if (blockIdx.x < W_BLOCKS) {
        const int n0 = (blockIdx.x & (N_DIM / 64 - 1)) * 64;
        const int k0 = (blockIdx.x / (N_DIM / 64)) * 64;

        const int lk = tid >> 4;
        const int ln = (tid & 15) << 2;
        #pragma unroll
        for (int i = 0; i < 4; i++) {
            int k = lk + i * 16;
            float4 v = *reinterpret_cast<const float4*>(
                w + (size_t)(k0 + k) * N_DIM + n0 + ln);
            float f[4] = {v.x, v.y, v.z, v.w};
            #pragma unroll
            for (int j = 0; j < 4; j++) {
                float hf = __half2float(__float2half_rn(f[j]));
                float s = (hf > 0.f) ? 1.f : ((hf < 0.f) ? -1.f : 0.f);
                t[ln + j][k] = __float2half_rn(s);
            }
        }
        __syncthreads();

        const int sn = tid >> 2;
        const int sk = (tid & 3) << 3;
        #pragma unroll
        for (int i = 0; i < 2; i++) {
            int kk = sk + i * 32;
            uint4 o = *reinterpret_cast<uint4*>(&t[sn][kk]);
            *reinterpret_cast<uint4*>(
                wbt + (size_t)(n0 + sn) * K_DIM + k0 + kk) = o;
        }
    } else {
        // x path: 16 consecutive floats per thread (4 LDG.128, 2 STG.128)
        const size_t base4 = ((size_t)(blockIdx.x - W_BLOCKS) * 256 + tid) * 4;
        float4 v[4];
        #pragma unroll
        for (int i = 0; i < 4; i++) v[i] = x[base4 + i];
        #pragma unroll
        for (int i = 0; i < 2; i++) {
            __half2 a = __floats2half2_rn(v[i*2].x,   v[i*2].y);
            __half2 b = __floats2half2_rn(v[i*2].z,   v[i*2].w);
            __half2 c = __floats2half2_rn(v[i*2+1].x, v[i*2+1].y);
            __half2 d = __floats2half2_rn(v[i*2+1].z, v[i*2+1].w);
            uint4 o;
            o.x = *reinterpret_cast<uint32_t*>(&a);
            o.y = *reinterpret_cast<uint32_t*>(&b);
            o.z = *reinterpret_cast<uint32_t*>(&c);
            o.w = *reinterpret_cast<uint32_t*>(&d);
            xh[base4 / 2 + i] = o;
        }
    }
}

// dummy launches: keep the GEMM at launch position 3 for ncu "-s 5 -c 1"
__global__ void prof_pad_kernel() {}
__global__ void prof_pad2_kernel() {}

// ------------------------------ PTX helpers -------------------------------
__device__ __forceinline__ uint32_t smem_u32(const void* p) {
    uint32_t a;
    asm("{ .reg .u64 t; cvta.to.shared.u64 t, %1; cvt.u32.u64 %0, t; }"
        : "=r"(a) : "l"(p));
    return a;
}

__device__ __forceinline__ uint32_t elect_one() {
    uint32_t pred;
    asm volatile(
        "{\n\t.reg .pred p;\n\t"
        "elect.sync _|p, 0xFFFFFFFF;\n\t"
        "selp.b32 %0, 1, 0, p;\n\t}"
        : "=r"(pred));
    return pred;
}

__device__ __forceinline__ void cp_async_16(uint32_t smem_dst, const void* gmem_src) {
    asm volatile("cp.async.cg.shared.global [%0], [%1], 16;"
                 :: "r"(smem_dst), "l"(gmem_src));
}

#define MBARRIER_INIT(addr, count) \
    asm volatile("mbarrier.init.shared.b64 [%0], %1;" \
                 :: "r"((uint32_t)(addr)), "r"((uint32_t)(count)) : "memory")

#define MBARRIER_ARRIVE(addr) \
    asm volatile("mbarrier.arrive.shared.b64 _, [%0];" \
                 :: "r"((uint32_t)(addr)) : "memory")

#define CPASYNC_MBAR_ARRIVE_NOINC(addr) \
    asm volatile("cp.async.mbarrier.arrive.noinc.shared.b64 [%0];" \
                 :: "r"((uint32_t)(addr)) : "memory")

#define MBARRIER_WAIT_PARITY(mbar_smem_addr, phase_parity) do { \
    uint32_t _mbar = (uint32_t)(mbar_smem_addr); \
    uint32_t _parity = (uint32_t)(phase_parity); \
    uint32_t _done; \
    asm volatile( \
        "{\n\t.reg .pred p;\n\t" \
        "mbarrier.try_wait.parity.acquire.cta.shared::cta.b64 p, [%1], %2;\n\t" \
        "selp.b32 %0, 1, 0, p;\n\t}" \
        : "=r"(_done) : "r"(_mbar), "r"(_parity) : "memory"); \
    if (!_done) { \
        asm volatile( \
            "{\n\t.reg .pred P1;\n\t" \
            "WAIT_LOOP_%=:\n\t" \
            "mbarrier.try_wait.parity.acquire.cta.shared::cta.b64 P1, [%0], %1, 0x989680;\n\t" \
            "@P1 bra.uni WAIT_DONE_%=;\n\t" \
            "bra.uni WAIT_LOOP_%=;\n\t" \
            "WAIT_DONE_%=:\n\t}" \
            :: "r"(_mbar), "r"(_parity) : "memory"); \
    } \
} while(0)

// elected single-lane wait + warp reconvergence
#define WARP_WAIT_PARITY(addr, parity) do { \
    if (elect_one()) { MBARRIER_WAIT_PARITY(addr, parity); } \
    __syncwarp(); \
} while (0)

__device__ __forceinline__ void ldmatrix_x4(uint32_t& r0, uint32_t& r1,
                                            uint32_t& r2, uint32_t& r3, uint32_t addr) {
    asm volatile("ldmatrix.sync.aligned.m8n8.x4.shared.b16 {%0,%1,%2,%3}, [%4];"
                 : "=r"(r0), "=r"(r1), "=r"(r2), "=r"(r3) : "r"(addr));
}

__device__ __forceinline__ void mma_16816(float* c, const uint32_t* a, const uint32_t* b) {
    asm volatile(
        "mma.sync.aligned.m16n8k16.row.col.f32.f16.f16.f32 "
        "{%0,%1,%2,%3}, {%4,%5,%6,%7}, {%8,%9}, {%0,%1,%2,%3};"
        : "+f"(c[0]), "+f"(c[1]), "+f"(c[2]), "+f"(c[3])
        : "r"(a[0]), "r"(a[1]), "r"(a[2]), "r"(a[3]), "r"(b[0]), "r"(b[1]));
}

// swizzle within a [rows][BK] fp16 tile, 128B rows: 16B chunk XOR (row & 7)
__device__ __forceinline__ uint32_t tile_off(int row, int chunk) {
    return (uint32_t)(row * 128 + ((chunk ^ (row & 7)) << 4));
}

// ------------------------------ GEMM kernel (R12) --------------------------
__global__ void __launch_bounds__(THREADS, 1) bgemm_mma_kernel(
    const __half* __restrict__ A,   // [M,K]
    const __half* __restrict__ B,   // [N,K]
    float* __restrict__ out)
{
    extern __shared__ uint8_t smem_raw[];
    uint32_t raw = smem_u32(smem_raw);
    const uint32_t hdr   = (raw + 1023u) & ~1023u;
    const uint32_t tiles = hdr + 1024u;

    #define FULL_BAR(s)  (hdr + (uint32_t)(s) * 8u)
    #define EMPTY_BAR(s) (hdr + 64u + (uint32_t)(s) * 8u)

    const int tid  = threadIdx.x;
    const int wid  = tid >> 5;
    const int lane = tid & 31;
    const int m0 = blockIdx.x * BM;
    const int n0 = blockIdx.y * BN;

    const int warp_m = wid & 3;   // 4 warps over M: 32 rows each
    const int warp_n = wid >> 2;  // 4 warps over N: 64 cols each

    const int ld_row0  = tid >> 3;   // 0..63
    const int ld_chunk = tid & 7;    // 0..7

    auto load_stage = [&](int slot, int kt) {
        const uint32_t sA = tiles + slot * STAGE_BYTES;
        const uint32_t sB = sA + A_TILE_BYTES;
        const int kcol = kt * BK + ld_chunk * 8;
        #pragma unroll
        for (int p = 0; p < 2; p++) {
            int row = ld_row0 + p * 64;
            cp_async_16(sA + tile_off(row, ld_chunk),
                        A + (size_t)(m0 + row) * K_DIM + kcol);
        }
        #pragma unroll
        for (int p = 0; p < 4; p++) {
            int row = ld_row0 + p * 64;
            cp_async_16(sB + tile_off(row, ld_chunk),
                        B + (size_t)(n0 + row) * K_DIM + kcol);
        }
        CPASYNC_MBAR_ARRIVE_NOINC(FULL_BAR(slot));
    };

    if (tid == 0) {
        #pragma unroll
        for (int s = 0; s < STAGES; s++) {
            MBARRIER_INIT(FULL_BAR(s), THREADS);
            MBARRIER_INIT(EMPTY_BAR(s), NWARPS);
        }
        asm volatile("fence.proxy.async.shared::cta;" ::: "memory");
    }
    __syncthreads();

    const int lrow = lane & 15;
    const int lsel = lane >> 4;

    uint32_t a_off[2], b_off[4];
    #pragma unroll
    for (int mi = 0; mi < 2; mi++)
        a_off[mi] = tile_off(warp_m * 32 + mi * 16 + lrow, lsel);
    #pragma unroll
    for (int nj = 0; nj < 4; nj++)
        b_off[nj] = tile_off(warp_n * 64 + nj * 16 + lrow, lsel);

    float acc[2][8][4];
    #pragma unroll
    for (int mi = 0; mi < 2; mi++)
        #pragma unroll
        for (int ni = 0; ni < 8; ni++)
            #pragma unroll
            for (int j = 0; j < 4; j++) acc[mi][ni][j] = 0.f;

    // prologue: fill stages 0..2
    #pragma unroll
    for (int s = 0; s < STAGES - 1; s++) {
        WARP_WAIT_PARITY(EMPTY_BAR(s), 1);
        load_stage(s, s);
    }

    for (int it = 0; it < NKI; it++) {
        const int s = it & 3;
        const uint32_t sA = tiles + s * STAGE_BYTES;
        const uint32_t sB = sA + A_TILE_BYTES;

        WARP_WAIT_PARITY(FULL_BAR(s), (it >> 2) & 1);

        #pragma unroll
        for (int kk = 0; kk < BK / 16; kk++) {
            const uint32_t kx = (uint32_t)kk << 5;

            uint32_t a[2][4];
            #pragma unroll
            for (int mi = 0; mi < 2; mi++)
                ldmatrix_x4(a[mi][0], a[mi][1], a[mi][2], a[mi][3],
                            (sA + a_off[mi]) ^ kx);
            uint32_t b[8][2];
            #pragma unroll
            for (int nj = 0; nj < 4; nj++) {
                uint32_t r0, r1, r2, r3;
                ldmatrix_x4(r0, r1, r2, r3, (sB + b_off[nj]) ^ kx);
                b[nj * 2 + 0][0] = r0; b[nj * 2 + 1][0] = r1;
                b[nj * 2 + 0][1] = r2; b[nj * 2 + 1][1] = r3;
            }

            if (kk == BK / 16 - 1) {
                __syncwarp();
                if (elect_one()) MBARRIER_ARRIVE(EMPTY_BAR(s));
            }

            #pragma unroll
            for (int mi = 0; mi < 2; mi++)
                #pragma unroll
                for (int ni = 0; ni < 8; ni++)
                    mma_16816(acc[mi][ni], a[mi], b[ni]);
        }

        const int kt = it + STAGES - 1;
        if (kt < NKI) {
            const int ps = kt & 3;
            WARP_WAIT_PARITY(EMPTY_BAR(ps), ((kt >> 2) & 1) ^ 1);
            load_stage(ps, kt);
        }
    }

    // ------------------------------ epilogue -------------------------------
    const int tq = lane >> 2;
    const int tp = lane & 3;
    #pragma unroll
    for (int mi = 0; mi < 2; mi++) {
        #pragma unroll
        for (int ni = 0; ni < 8; ni++) {
            int r = m0 + warp_m * 32 + mi * 16 + tq;
            int c = n0 + warp_n * 64 + ni * 8 + tp * 2;
            float2 v0 = make_float2(acc[mi][ni][0], acc[mi][ni][1]);
            float2 v1 = make_float2(acc[mi][ni][2], acc[mi][ni][3]);
            *reinterpret_cast<float2*>(out + (size_t)r * N_DIM + c) = v0;
            *reinterpret_cast<float2*>(out + (size_t)(r + 8) * N_DIM + c) = v1;
        }
    }
}

// ------------------------------- host side --------------------------------
extern "C" void kernel_launch(void* const* d_in, const int* in_sizes, int n_in,
                              void* d_out, int out_size)
{
    const float* x = (const float*)d_in[0];
    const float* w = (const float*)d_in[1];
    float* out = (float*)d_out;

    void *xh_ptr = nullptr, *wbt_ptr = nullptr;
    cudaGetSymbolAddress(&xh_ptr, g_xh);
    cudaGetSymbolAddress(&wbt_ptr, g_wbt);

    // fused converts: w-transpose blocks + x-convert blocks in one launch
    cvt_fused_kernel<<<W_BLOCKS + X_BLOCKS, 256>>>(
        (const float4*)x, (uint4*)xh_ptr, w, (__half*)wbt_ptr);

    // pads keep the GEMM at launch position 3 (proven ncu -s 5 alignment)
    prof_pad_kernel<<<1, 32>>>();
    prof_pad2_kernel<<<1, 32>>>();

    cudaFuncSetAttribute(bgemm_mma_kernel,
                         cudaFuncAttributeMaxDynamicSharedMemorySize, SMEM_DYN);

    dim3 grid(M_DIM / BM, N_DIM / BN);  // (64, 16)
    bgemm_mma_kernel<<<grid, THREADS, SMEM_DYN>>>(
        (const __half*)xh_ptr, (const __half*)wbt_ptr, out);
}

// round 16
// speedup vs baseline: 1.1329x; 1.0039x over previous
#include <cuda_runtime.h>
#include <cuda_fp16.h>
#include <cstdint>

// ---------------------------------------------------------------------------
// out[8192,4096] = x[8192,4096]_fp32 @ sign(fp16(w[4096,4096]))
//
// R16 (floor config): GEMM = R12 exactly -- 100.0% of the measured legacy
// HMMA issue wall (rt ~11.6 cyc/SMSP, acc-type invariant; 67.1M HMMAs ->
// 691us). Fused convert kernel (bandwidth floor ~46us) + ZERO pad launches:
// 2-launch period puts ncu "-s 5" on the GEMM automatically. w-path sign via
// bit trick (value-identical).
// ---------------------------------------------------------------------------

#define M_DIM 8192
#define N_DIM 4096
#define K_DIM 4096

#define BM 128
#define BN 256
#define BK 64
#define STAGES 4
#define THREADS 512
#define NWARPS (THREADS / 32)
#define NKI (K_DIM / BK)   // 64

#define A_TILE_BYTES (BM * BK * 2)            // 16384
#define B_TILE_BYTES (BN * BK * 2)            // 32768
#define STAGE_BYTES  (A_TILE_BYTES + B_TILE_BYTES)   // 49152
#define SMEM_DYN     (1024 + 1024 + STAGES * STAGE_BYTES)  // 198656

#define W_BLOCKS ((N_DIM / 64) * (K_DIM / 64))          // 4096
#define X_BLOCKS ((M_DIM * K_DIM) / (256 * 16))         // 8192

// ------------------------------ scratch -----------------------------------
__device__ __align__(1024) __half g_xh[(size_t)M_DIM * K_DIM];   // 64 MB
__device__ __align__(1024) __half g_wbt[(size_t)N_DIM * K_DIM];  // 32 MB

// --------------------------- fused convert kernel ---------------------------
// blocks [0, W_BLOCKS): w[K,N] fp32 -> wbt[N,K] fp16 sign(fp16(w)), 64x64 tile
// blocks [W_BLOCKS, ...): x fp32 -> fp16, 16 floats/thread
__global__ void __launch_bounds__(256, 8) cvt_fused_kernel(
    const float4* __restrict__ x, uint4* __restrict__ xh,
    const float*  __restrict__ w, __half* __restrict__ wbt)
{
    __shared__ __half t[64][72];
    const int tid = threadIdx.x;

    if (blockIdx.x < W_BLOCKS) {
        const int n0 = (blockIdx.x & (N_DIM / 64 - 1)) * 64;
        const int k0 = (blockIdx.x / (N_DIM / 64)) * 64;

        const int lk = tid >> 4;
        const int ln = (tid & 15) << 2;
        #pragma unroll
        for (int i = 0; i < 4; i++) {
            int k = lk + i * 16;
            float4 v = *reinterpret_cast<const float4*>(
                w + (size_t)(k0 + k) * N_DIM + n0 + ln);
            float f[4] = {v.x, v.y, v.z, v.w};
            #pragma unroll
            for (int j = 0; j < 4; j++) {
                // sign(fp16(w)) via bits: +-1 = 0x3C00|signbit, +-0 -> 0
                __half h = __float2half_rn(f[j]);
                uint16_t hb = *reinterpret_cast<uint16_t*>(&h);
                uint16_t sb = (uint16_t)((hb & 0x7FFF) ? ((hb & 0x8000) | 0x3C00) : 0);
                t[ln + j][k] = *reinterpret_cast<__half*>(&sb);
            }
        }
        __syncthreads();

        const int sn = tid >> 2;
        const int sk = (tid & 3) << 3;
        #pragma unroll
        for (int i = 0; i < 2; i++) {
            int kk = sk + i * 32;
            uint4 o = *reinterpret_cast<uint4*>(&t[sn][kk]);
            *reinterpret_cast<uint4*>(
                wbt + (size_t)(n0 + sn) * K_DIM + k0 + kk) = o;
        }
    } else {
        // x path: 16 consecutive floats per thread (4 LDG.128, 2 STG.128)
        const size_t base4 = ((size_t)(blockIdx.x - W_BLOCKS) * 256 + tid) * 4;
        float4 v[4];
        #pragma unroll
        for (int i = 0; i < 4; i++) v[i] = x[base4 + i];
        #pragma unroll
        for (int i = 0; i < 2; i++) {
            __half2 a = __floats2half2_rn(v[i*2].x,   v[i*2].y);
            __half2 b = __floats2half2_rn(v[i*2].z,   v[i*2].w);
            __half2 c = __floats2half2_rn(v[i*2+1].x, v[i*2+1].y);
            __half2 d = __floats2half2_rn(v[i*2+1].z, v[i*2+1].w);
            uint4 o;
            o.x = *reinterpret_cast<uint32_t*>(&a);
            o.y = *reinterpret_cast<uint32_t*>(&b);
            o.z = *reinterpret_cast<uint32_t*>(&c);
            o.w = *reinterpret_cast<uint32_t*>(&d);
            xh[base4 / 2 + i] = o;
        }
    }
}

// ------------------------------ PTX helpers -------------------------------
__device__ __forceinline__ uint32_t smem_u32(const void* p) {
    uint32_t a;
    asm("{ .reg .u64 t; cvta.to.shared.u64 t, %1; cvt.u32.u64 %0, t; }"
        : "=r"(a) : "l"(p));
    return a;
}

__device__ __forceinline__ uint32_t elect_one() {
    uint32_t pred;
    asm volatile(
        "{\n\t.reg .pred p;\n\t"
        "elect.sync _|p, 0xFFFFFFFF;\n\t"
        "selp.b32 %0, 1, 0, p;\n\t}"
        : "=r"(pred));
    return pred;
}

__device__ __forceinline__ void cp_async_16(uint32_t smem_dst, const void* gmem_src) {
    asm volatile("cp.async.cg.shared.global [%0], [%1], 16;"
                 :: "r"(smem_dst), "l"(gmem_src));
}

#define MBARRIER_INIT(addr, count) \
    asm volatile("mbarrier.init.shared.b64 [%0], %1;" \
                 :: "r"((uint32_t)(addr)), "r"((uint32_t)(count)) : "memory")

#define MBARRIER_ARRIVE(addr) \
    asm volatile("mbarrier.arrive.shared.b64 _, [%0];" \
                 :: "r"((uint32_t)(addr)) : "memory")

#define CPASYNC_MBAR_ARRIVE_NOINC(addr) \
    asm volatile("cp.async.mbarrier.arrive.noinc.shared.b64 [%0];" \
                 :: "r"((uint32_t)(addr)) : "memory")

#define MBARRIER_WAIT_PARITY(mbar_smem_addr, phase_parity) do { \
    uint32_t _mbar = (uint32_t)(mbar_smem_addr); \
    uint32_t _parity = (uint32_t)(phase_parity); \
    uint32_t _done; \
    asm volatile( \
        "{\n\t.reg .pred p;\n\t" \
        "mbarrier.try_wait.parity.acquire.cta.shared::cta.b64 p, [%1], %2;\n\t" \
        "selp.b32 %0, 1, 0, p;\n\t}" \
        : "=r"(_done) : "r"(_mbar), "r"(_parity) : "memory"); \
    if (!_done) { \
        asm volatile( \
            "{\n\t.reg .pred P1;\n\t" \
            "WAIT_LOOP_%=:\n\t" \
            "mbarrier.try_wait.parity.acquire.cta.shared::cta.b64 P1, [%0], %1, 0x989680;\n\t" \
            "@P1 bra.uni WAIT_DONE_%=;\n\t" \
            "bra.uni WAIT_LOOP_%=;\n\t" \
            "WAIT_DONE_%=:\n\t}" \
            :: "r"(_mbar), "r"(_parity) : "memory"); \
    } \
} while(0)

// elected single-lane wait + warp reconvergence
#define WARP_WAIT_PARITY(addr, parity) do { \
    if (elect_one()) { MBARRIER_WAIT_PARITY(addr, parity); } \
    __syncwarp(); \
} while (0)

__device__ __forceinline__ void ldmatrix_x4(uint32_t& r0, uint32_t& r1,
                                            uint32_t& r2, uint32_t& r3, uint32_t addr) {
    asm volatile("ldmatrix.sync.aligned.m8n8.x4.shared.b16 {%0,%1,%2,%3}, [%4];"
                 : "=r"(r0), "=r"(r1), "=r"(r2), "=r"(r3) : "r"(addr));
}

__device__ __forceinline__ void mma_16816(float* c, const uint32_t* a, const uint32_t* b) {
    asm volatile(
        "mma.sync.aligned.m16n8k16.row.col.f32.f16.f16.f32 "
        "{%0,%1,%2,%3}, {%4,%5,%6,%7}, {%8,%9}, {%0,%1,%2,%3};"
        : "+f"(c[0]), "+f"(c[1]), "+f"(c[2]), "+f"(c[3])
        : "r"(a[0]), "r"(a[1]), "r"(a[2]), "r"(a[3]), "r"(b[0]), "r"(b[1]));
}

// swizzle within a [rows][BK] fp16 tile, 128B rows: 16B chunk XOR (row & 7)
__device__ __forceinline__ uint32_t tile_off(int row, int chunk) {
    return (uint32_t)(row * 128 + ((chunk ^ (row & 7)) << 4));
}

// ------------------------------ GEMM kernel (R12) --------------------------
__global__ void __launch_bounds__(THREADS, 1) bgemm_mma_kernel(
    const __half* __restrict__ A,   // [M,K]
    const __half* __restrict__ B,   // [N,K]
    float* __restrict__ out)
{
    extern __shared__ uint8_t smem_raw[];
    uint32_t raw = smem_u32(smem_raw);
    const uint32_t hdr   = (raw + 1023u) & ~1023u;
    const uint32_t tiles = hdr + 1024u;

    #define FULL_BAR(s)  (hdr + (uint32_t)(s) * 8u)
    #define EMPTY_BAR(s) (hdr + 64u + (uint32_t)(s) * 8u)

    const int tid  = threadIdx.x;
    const int wid  = tid >> 5;
    const int lane = tid & 31;
    const int m0 = blockIdx.x * BM;
    const int n0 = blockIdx.y * BN;

    const int warp_m = wid & 3;   // 4 warps over M: 32 rows each
    const int warp_n = wid >> 2;  // 4 warps over N: 64 cols each

    const int ld_row0  = tid >> 3;   // 0..63
    const int ld_chunk = tid & 7;    // 0..7

    auto load_stage = [&](int slot, int kt) {
        const uint32_t sA = tiles + slot * STAGE_BYTES;
        const uint32_t sB = sA + A_TILE_BYTES;
        const int kcol = kt * BK + ld_chunk * 8;
        #pragma unroll
        for (int p = 0; p < 2; p++) {
            int row = ld_row0 + p * 64;
            cp_async_16(sA + tile_off(row, ld_chunk),
                        A + (size_t)(m0 + row) * K_DIM + kcol);
        }
        #pragma unroll
        for (int p = 0; p < 4; p++) {
            int row = ld_row0 + p * 64;
            cp_async_16(sB + tile_off(row, ld_chunk),
                        B + (size_t)(n0 + row) * K_DIM + kcol);
        }
        CPASYNC_MBAR_ARRIVE_NOINC(FULL_BAR(slot));
    };

    if (tid == 0) {
        #pragma unroll
        for (int s = 0; s < STAGES; s++) {
            MBARRIER_INIT(FULL_BAR(s), THREADS);
            MBARRIER_INIT(EMPTY_BAR(s), NWARPS);
        }
        asm volatile("fence.proxy.async.shared::cta;" ::: "memory");
    }
    __syncthreads();

    const int lrow = lane & 15;
    const int lsel = lane >> 4;

    uint32_t a_off[2], b_off[4];
    #pragma unroll
    for (int mi = 0; mi < 2; mi++)
        a_off[mi] = tile_off(warp_m * 32 + mi * 16 + lrow, lsel);
    #pragma unroll
    for (int nj = 0; nj < 4; nj++)
        b_off[nj] = tile_off(warp_n * 64 + nj * 16 + lrow, lsel);

    float acc[2][8][4];
    #pragma unroll
    for (int mi = 0; mi < 2; mi++)
        #pragma unroll
        for (int ni = 0; ni < 8; ni++)
            #pragma unroll
            for (int j = 0; j < 4; j++) acc[mi][ni][j] = 0.f;

    // prologue: fill stages 0..2
    #pragma unroll
    for (int s = 0; s < STAGES - 1; s++) {
        WARP_WAIT_PARITY(EMPTY_BAR(s), 1);
        load_stage(s, s);
    }

    for (int it = 0; it < NKI; it++) {
        const int s = it & 3;
        const uint32_t sA = tiles + s * STAGE_BYTES;
        const uint32_t sB = sA + A_TILE_BYTES;

        WARP_WAIT_PARITY(FULL_BAR(s), (it >> 2) & 1);

        #pragma unroll
        for (int kk = 0; kk < BK / 16; kk++) {
            const uint32_t kx = (uint32_t)kk << 5;

            uint32_t a[2][4];
            #pragma unroll
            for (int mi = 0; mi < 2; mi++)
                ldmatrix_x4(a[mi][0], a[mi][1], a[mi][2], a[mi][3],
                            (sA + a_off[mi]) ^ kx);
            uint32_t b[8][2];
            #pragma unroll
            for (int nj = 0; nj < 4; nj++) {
                uint32_t r0, r1, r2, r3;
                ldmatrix_x4(r0, r1, r2, r3, (sB + b_off[nj]) ^ kx);
                b[nj * 2 + 0][0] = r0; b[nj * 2 + 1][0] = r1;
                b[nj * 2 + 0][1] = r2; b[nj * 2 + 1][1] = r3;
            }

            if (kk == BK / 16 - 1) {
                __syncwarp();
                if (elect_one()) MBARRIER_ARRIVE(EMPTY_BAR(s));
            }

            #pragma unroll
            for (int mi = 0; mi < 2; mi++)
                #pragma unroll
                for (int ni = 0; ni < 8; ni++)
                    mma_16816(acc[mi][ni], a[mi], b[ni]);
        }

        const int kt = it + STAGES - 1;
        if (kt < NKI) {
            const int ps = kt & 3;
            WARP_WAIT_PARITY(EMPTY_BAR(ps), ((kt >> 2) & 1) ^ 1);
            load_stage(ps, kt);
        }
    }

    // ------------------------------ epilogue -------------------------------
    const int tq = lane >> 2;
    const int tp = lane & 3;
    #pragma unroll
    for (int mi = 0; mi < 2; mi++) {
        #pragma unroll
        for (int ni = 0; ni < 8; ni++) {
            int r = m0 + warp_m * 32 + mi * 16 + tq;
            int c = n0 + warp_n * 64 + ni * 8 + tp * 2;
            float2 v0 = make_float2(acc[mi][ni][0], acc[mi][ni][1]);
            float2 v1 = make_float2(acc[mi][ni][2], acc[mi][ni][3]);
            *reinterpret_cast<float2*>(out + (size_t)r * N_DIM + c) = v0;
            *reinterpret_cast<float2*>(out + (size_t)(r + 8) * N_DIM + c) = v1;
        }
    }
}

// ------------------------------- host side --------------------------------
extern "C" void kernel_launch(void* const* d_in, const int* in_sizes, int n_in,
                              void* d_out, int out_size)
{
    const float* x = (const float*)d_in[0];
    const float* w = (const float*)d_in[1];
    float* out = (float*)d_out;

    void *xh_ptr = nullptr, *wbt_ptr = nullptr;
    cudaGetSymbolAddress(&xh_ptr, g_xh);
    cudaGetSymbolAddress(&wbt_ptr, g_wbt);

    // one fused convert launch; two-launch period puts ncu "-s 5" (odd
    // index) on the GEMM with no pad kernels
    cvt_fused_kernel<<<W_BLOCKS + X_BLOCKS, 256>>>(
        (const float4*)x, (uint4*)xh_ptr, w, (__half*)wbt_ptr);

    cudaFuncSetAttribute(bgemm_mma_kernel,
                         cudaFuncAttributeMaxDynamicSharedMemorySize, SMEM_DYN);

    dim3 grid(M_DIM / BM, N_DIM / BN);  // (64, 16)
    bgemm_mma_kernel<<<grid, THREADS, SMEM_DYN>>>(
        (const __half*)xh_ptr, (const __half*)wbt_ptr, out);
}